// round 1
// baseline (speedup 1.0000x reference)
#include <cuda_runtime.h>
#include <math.h>

#define BB 2
#define SS 2048
#define DD 2048
#define NH 32
#define NKV 8
#define HD 64
#define RATIO 4
#define MROWS (BB * SS)   // 4096

// ---------------- scratch (no allocations allowed) ----------------
__device__ float g_q[(size_t)BB * NH * SS * HD];    // [B, NH, S, HD]
__device__ float g_k[(size_t)BB * NKV * SS * HD];   // [B, NKV, S, HD]
__device__ float g_v[(size_t)BB * NKV * SS * HD];   // [B, NKV, S, HD]
__device__ float g_o[(size_t)MROWS * (NH * HD)];    // [B*S, NH*HD]

// =====================================================================
// Projection GEMM: C[64 rows x 64 cols(=1 head)] = X @ W, with optional
// fused RMSNorm + RoPE epilogue. Tile: BM=64, BN=64(=HD), BK=16.
// 256 threads, 4x4 per-thread microtile.
// grid = (MROWS/64, n_heads)
// =====================================================================
__global__ void __launch_bounds__(256)
proj_kernel(const float* __restrict__ x, const float* __restrict__ w,
            const float* __restrict__ scale, const float* __restrict__ cosp,
            const float* __restrict__ sinp, float* __restrict__ out,
            int n_heads, int apply_rope)
{
    __shared__ float As[64][17];
    __shared__ __align__(16) float Bs[16][64];
    __shared__ float Cs[64][65];

    const int tid = threadIdx.x;
    const int tx = tid & 15;       // 0..15 (N dir)
    const int ty = tid >> 4;       // 0..15 (M dir)
    const int row0 = blockIdx.x * 64;
    const int h = blockIdx.y;
    const int Nw = n_heads * HD;
    const int col0 = h * HD;

    float acc[4][4] = {};

    for (int k0 = 0; k0 < DD; k0 += 16) {
        #pragma unroll
        for (int l = 0; l < 4; l++) {
            int idx = tid + l * 256;            // 0..1023
            int m = idx >> 4, kk = idx & 15;
            As[m][kk] = x[(size_t)(row0 + m) * DD + k0 + kk];
        }
        #pragma unroll
        for (int l = 0; l < 4; l++) {
            int idx = tid + l * 256;
            int kk = idx >> 6, n = idx & 63;
            Bs[kk][n] = w[(size_t)(k0 + kk) * Nw + col0 + n];
        }
        __syncthreads();
        #pragma unroll
        for (int kk = 0; kk < 16; kk++) {
            float a[4];
            #pragma unroll
            for (int i = 0; i < 4; i++) a[i] = As[ty * 4 + i][kk];
            float4 bv = *(const float4*)&Bs[kk][tx * 4];
            float bb[4] = {bv.x, bv.y, bv.z, bv.w};
            #pragma unroll
            for (int i = 0; i < 4; i++)
                #pragma unroll
                for (int j = 0; j < 4; j++)
                    acc[i][j] += a[i] * bb[j];
        }
        __syncthreads();
    }

    const int bidx = row0 / SS;
    const int s0 = row0 % SS;      // block never straddles a batch boundary

    if (!apply_rope) {
        // V path: straight transpose store to [B, NKV, S, HD]
        #pragma unroll
        for (int i = 0; i < 4; i++) {
            int s = s0 + ty * 4 + i;
            size_t base = (((size_t)bidx * n_heads + h) * SS + s) * HD;
            #pragma unroll
            for (int j = 0; j < 4; j++)
                out[base + tx * 4 + j] = acc[i][j];
        }
        return;
    }

    // stage tile to smem for row-wise RMSNorm + RoPE
    #pragma unroll
    for (int i = 0; i < 4; i++)
        #pragma unroll
        for (int j = 0; j < 4; j++)
            Cs[ty * 4 + i][tx * 4 + j] = acc[i][j];
    __syncthreads();

    const int r = tid >> 2;        // 0..63 row
    const int sub = tid & 3;       // 4 threads per row
    float ss = 0.0f;
    #pragma unroll
    for (int c = 0; c < 16; c++) {
        float v = Cs[r][sub * 16 + c];
        ss += v * v;
    }
    ss += __shfl_xor_sync(0xffffffff, ss, 1);
    ss += __shfl_xor_sync(0xffffffff, ss, 2);
    const float inv = rsqrtf(ss * (1.0f / HD) + 1e-6f);

    const int sg = s0 + r;
    const float* cr = cosp + (size_t)sg * HD;
    const float* sr = sinp + (size_t)sg * HD;
    const size_t obase = (((size_t)bidx * n_heads + h) * SS + sg) * HD;
    #pragma unroll
    for (int cc = 0; cc < 16; cc++) {
        int c = sub * 16 + cc;
        int p = (c + 32) & 63;
        float v  = Cs[r][c] * inv * scale[c];
        float pv = Cs[r][p] * inv * scale[p];
        float sign = (c < 32) ? -1.0f : 1.0f;
        out[obase + c] = v * cr[c] + sign * pv * sr[c];
    }
}

// =====================================================================
// Flash attention, fp32, causal. One CTA handles 64 query rows of one
// (b, h). Online softmax. grid = (S/64, B*NH), 256 threads.
// =====================================================================
__global__ void __launch_bounds__(256)
attn_kernel(const float* __restrict__ q, const float* __restrict__ k,
            const float* __restrict__ v, float* __restrict__ o_out)
{
    extern __shared__ float sm[];
    float* Qs   = sm;               // 64*65
    float* Ks   = Qs + 64 * 65;     // 64*65
    float* Ps   = Ks + 64 * 65;     // 64*65
    float* Vs   = Ps + 64 * 65;     // 64*64 (float4-aligned reads)
    float* red  = Vs + 64 * 64;     // 64*16
    float* rowm = red + 64 * 16;    // 64
    float* rowl = rowm + 64;        // 64
    float* alph = rowl + 64;        // 64

    const int tid = threadIdx.x;
    const int tx = tid & 15, ty = tid >> 4;
    const int qb = blockIdx.x;
    const int bh = blockIdx.y;
    const int b = bh / NH, h = bh % NH, hk = h / RATIO;

    const size_t qbase = (((size_t)b * NH + h) * SS + (size_t)qb * 64) * HD;
    const size_t kvbase = ((size_t)b * NKV + hk) * SS * HD;

    #pragma unroll
    for (int l = 0; l < 16; l++) {
        int idx = tid + l * 256;
        int r = idx >> 6, d = idx & 63;
        Qs[r * 65 + d] = q[qbase + (size_t)r * HD + d] * 0.125f; // 1/sqrt(64)
    }
    if (tid < 64) { rowm[tid] = -1e30f; rowl[tid] = 0.0f; }
    float o[4][4] = {};
    __syncthreads();

    for (int kb = 0; kb <= qb; kb++) {
        const size_t kt = kvbase + (size_t)kb * 64 * HD;
        #pragma unroll
        for (int l = 0; l < 16; l++) {
            int idx = tid + l * 256;
            int r = idx >> 6, d = idx & 63;
            Ks[r * 65 + d] = k[kt + (size_t)r * HD + d];
            Vs[r * 64 + d] = v[kt + (size_t)r * HD + d];
        }
        __syncthreads();

        // S = Q K^T
        float sv[4][4] = {};
        #pragma unroll 8
        for (int d = 0; d < 64; d++) {
            float a[4], bb[4];
            #pragma unroll
            for (int i = 0; i < 4; i++) a[i]  = Qs[(ty * 4 + i) * 65 + d];
            #pragma unroll
            for (int j = 0; j < 4; j++) bb[j] = Ks[(tx * 4 + j) * 65 + d];
            #pragma unroll
            for (int i = 0; i < 4; i++)
                #pragma unroll
                for (int j = 0; j < 4; j++)
                    sv[i][j] += a[i] * bb[j];
        }

        if (kb == qb) {  // causal mask inside the diagonal block
            #pragma unroll
            for (int i = 0; i < 4; i++)
                #pragma unroll
                for (int j = 0; j < 4; j++)
                    if (tx * 4 + j > ty * 4 + i) sv[i][j] = -1e30f;
        }

        // per-row max
        #pragma unroll
        for (int i = 0; i < 4; i++) {
            float tm = fmaxf(fmaxf(sv[i][0], sv[i][1]), fmaxf(sv[i][2], sv[i][3]));
            red[(ty * 4 + i) * 16 + tx] = tm;
        }
        __syncthreads();
        if (tid < 64) {
            float tm = red[tid * 16];
            #pragma unroll
            for (int t = 1; t < 16; t++) tm = fmaxf(tm, red[tid * 16 + t]);
            float mo = rowm[tid];
            float mn = fmaxf(mo, tm);
            alph[tid] = __expf(mo - mn);
            rowm[tid] = mn;
        }
        __syncthreads();

        // P = exp(S - m), partial row sums
        #pragma unroll
        for (int i = 0; i < 4; i++) {
            float mr = rowm[ty * 4 + i];
            float ps = 0.0f;
            #pragma unroll
            for (int j = 0; j < 4; j++) {
                float p = __expf(sv[i][j] - mr);
                Ps[(ty * 4 + i) * 65 + tx * 4 + j] = p;
                ps += p;
            }
            red[(ty * 4 + i) * 16 + tx] = ps;
        }
        __syncthreads();
        if (tid < 64) {
            float ssum = 0.0f;
            #pragma unroll
            for (int t = 0; t < 16; t++) ssum += red[tid * 16 + t];
            rowl[tid] = rowl[tid] * alph[tid] + ssum;
        }

        // rescale O, then O += P V
        #pragma unroll
        for (int i = 0; i < 4; i++) {
            float al = alph[ty * 4 + i];
            #pragma unroll
            for (int j = 0; j < 4; j++) o[i][j] *= al;
        }
        #pragma unroll 4
        for (int kk = 0; kk < 64; kk++) {
            float4 bv = *(const float4*)&Vs[kk * 64 + tx * 4];
            float bb[4] = {bv.x, bv.y, bv.z, bv.w};
            #pragma unroll
            for (int i = 0; i < 4; i++) {
                float a = Ps[(ty * 4 + i) * 65 + kk];
                #pragma unroll
                for (int j = 0; j < 4; j++) o[i][j] += a * bb[j];
            }
        }
        __syncthreads();
    }

    #pragma unroll
    for (int i = 0; i < 4; i++) {
        int r = ty * 4 + i;
        float inv = 1.0f / rowl[r];
        size_t orow = ((size_t)b * SS + (size_t)qb * 64 + r) * (NH * HD) + (size_t)h * HD;
        #pragma unroll
        for (int j = 0; j < 4; j++)
            o_out[orow + tx * 4 + j] = o[i][j] * inv;
    }
}

// =====================================================================
// Output GEMM: out[4096,2048] = g_o @ wo
// =====================================================================
__global__ void __launch_bounds__(256)
gemm_out_kernel(const float* __restrict__ A, const float* __restrict__ W,
                float* __restrict__ C)
{
    __shared__ float As[64][17];
    __shared__ __align__(16) float Bs[16][64];

    const int tid = threadIdx.x;
    const int tx = tid & 15, ty = tid >> 4;
    const int row0 = blockIdx.x * 64;
    const int col0 = blockIdx.y * 64;
    const int Nw = NH * HD; // 2048

    float acc[4][4] = {};

    for (int k0 = 0; k0 < (NH * HD); k0 += 16) {
        #pragma unroll
        for (int l = 0; l < 4; l++) {
            int idx = tid + l * 256;
            int m = idx >> 4, kk = idx & 15;
            As[m][kk] = A[(size_t)(row0 + m) * Nw + k0 + kk];
        }
        #pragma unroll
        for (int l = 0; l < 4; l++) {
            int idx = tid + l * 256;
            int kk = idx >> 6, n = idx & 63;
            Bs[kk][n] = W[(size_t)(k0 + kk) * DD + col0 + n];
        }
        __syncthreads();
        #pragma unroll
        for (int kk = 0; kk < 16; kk++) {
            float a[4];
            #pragma unroll
            for (int i = 0; i < 4; i++) a[i] = As[ty * 4 + i][kk];
            float4 bv = *(const float4*)&Bs[kk][tx * 4];
            float bb[4] = {bv.x, bv.y, bv.z, bv.w};
            #pragma unroll
            for (int i = 0; i < 4; i++)
                #pragma unroll
                for (int j = 0; j < 4; j++)
                    acc[i][j] += a[i] * bb[j];
        }
        __syncthreads();
    }

    #pragma unroll
    for (int i = 0; i < 4; i++) {
        size_t rbase = (size_t)(row0 + ty * 4 + i) * DD + col0;
        #pragma unroll
        for (int j = 0; j < 4; j++)
            C[rbase + tx * 4 + j] = acc[i][j];
    }
}

// =====================================================================
extern "C" void kernel_launch(void* const* d_in, const int* in_sizes, int n_in,
                              void* d_out, int out_size)
{
    const float* x       = (const float*)d_in[0];
    const float* wq      = (const float*)d_in[1];
    const float* wk      = (const float*)d_in[2];
    const float* wv      = (const float*)d_in[3];
    const float* wo      = (const float*)d_in[4];
    const float* q_scale = (const float*)d_in[5];
    const float* k_scale = (const float*)d_in[6];
    const float* cosp    = (const float*)d_in[7];
    const float* sinp    = (const float*)d_in[8];
    // d_in[9] = mask (causal, reconstructed in-kernel)

    float *gq, *gk, *gv, *go;
    cudaGetSymbolAddress((void**)&gq, g_q);
    cudaGetSymbolAddress((void**)&gk, g_k);
    cudaGetSymbolAddress((void**)&gv, g_v);
    cudaGetSymbolAddress((void**)&go, g_o);

    dim3 blk(256);

    // Q, K projections with fused RMSNorm + RoPE; V plain transpose
    proj_kernel<<<dim3(MROWS / 64, NH),  blk>>>(x, wq, q_scale, cosp, sinp, gq, NH,  1);
    proj_kernel<<<dim3(MROWS / 64, NKV), blk>>>(x, wk, k_scale, cosp, sinp, gk, NKV, 1);
    proj_kernel<<<dim3(MROWS / 64, NKV), blk>>>(x, wv, nullptr, nullptr, nullptr, gv, NKV, 0);

    // attention
    size_t smem = (size_t)(64 * 65 * 3 + 64 * 64 + 64 * 16 + 64 * 3) * sizeof(float);
    cudaFuncSetAttribute(attn_kernel, cudaFuncAttributeMaxDynamicSharedMemorySize, (int)smem);
    attn_kernel<<<dim3(SS / 64, BB * NH), blk, smem>>>(gq, gk, gv, go);

    // output projection
    gemm_out_kernel<<<dim3(MROWS / 64, DD / 64), blk>>>(go, wo, (float*)d_out);
}

// round 4
// speedup vs baseline: 1.6677x; 1.6677x over previous
#include <cuda_runtime.h>
#include <cuda_bf16.h>
#include <math.h>
#include <stdint.h>

#define BB 2
#define SS 2048
#define DD 2048
#define NH 32
#define NKV 8
#define HD 64
#define RATIO 4
#define MROWS (BB * SS)   // 4096

// ===================== helpers =====================
__device__ __forceinline__ uint32_t smem_u32(const void* p) {
    uint32_t a;
    asm("{ .reg .u64 t; cvta.to.shared.u64 t, %1; cvt.u32.u64 %0, t; }"
        : "=r"(a) : "l"(p));
    return a;
}
__device__ __forceinline__ void cp16(uint32_t dst, const void* src) {
    asm volatile("cp.async.cg.shared.global [%0], [%1], 16;" :: "r"(dst), "l"(src));
}
#define CP_COMMIT() asm volatile("cp.async.commit_group;" ::: "memory")
#define CP_WAIT1()  asm volatile("cp.async.wait_group 1;" ::: "memory")

__device__ __forceinline__ void ldm_x4(uint32_t* r, uint32_t addr) {
    asm volatile("ldmatrix.sync.aligned.m8n8.x4.shared.b16 {%0,%1,%2,%3}, [%4];"
                 : "=r"(r[0]), "=r"(r[1]), "=r"(r[2]), "=r"(r[3]) : "r"(addr));
}
__device__ __forceinline__ void mma_bf16(float* d, const uint32_t* a, const uint32_t* b) {
    asm volatile("mma.sync.aligned.m16n8k16.row.col.f32.bf16.bf16.f32 "
                 "{%0,%1,%2,%3}, {%4,%5,%6,%7}, {%8,%9}, {%0,%1,%2,%3};"
                 : "+f"(d[0]), "+f"(d[1]), "+f"(d[2]), "+f"(d[3])
                 : "r"(a[0]), "r"(a[1]), "r"(a[2]), "r"(a[3]), "r"(b[0]), "r"(b[1]));
}

// ===================== scratch =====================
__device__ __nv_bfloat16 g_xhi[(size_t)MROWS * DD];
__device__ __nv_bfloat16 g_xlo[(size_t)MROWS * DD];
__device__ __nv_bfloat16 g_wqh[(size_t)(NH * HD) * DD];
__device__ __nv_bfloat16 g_wql[(size_t)(NH * HD) * DD];
__device__ __nv_bfloat16 g_wkh[(size_t)(NKV * HD) * DD];
__device__ __nv_bfloat16 g_wkl[(size_t)(NKV * HD) * DD];
__device__ __nv_bfloat16 g_wvh[(size_t)(NKV * HD) * DD];
__device__ __nv_bfloat16 g_wvl[(size_t)(NKV * HD) * DD];
__device__ __nv_bfloat16 g_woh[(size_t)DD * (NH * HD)];
__device__ __nv_bfloat16 g_wol[(size_t)DD * (NH * HD)];
__device__ float g_q[(size_t)BB * NH * SS * HD];
__device__ float g_k[(size_t)BB * NKV * SS * HD];
__device__ float g_v[(size_t)BB * NKV * SS * HD];
__device__ float g_o[(size_t)MROWS * (NH * HD)];
__device__ __nv_bfloat16 g_ohi[(size_t)MROWS * (NH * HD)];
__device__ __nv_bfloat16 g_olo[(size_t)MROWS * (NH * HD)];

// ===================== conversion kernels =====================
__global__ void __launch_bounds__(256)
split_kernel(const float* __restrict__ src, __nv_bfloat16* __restrict__ hi,
             __nv_bfloat16* __restrict__ lo, int n4)
{
    int i = blockIdx.x * 256 + threadIdx.x;
    if (i >= n4) return;
    float4 f = ((const float4*)src)[i];
    float fs[4] = {f.x, f.y, f.z, f.w};
    __nv_bfloat16 h[4], l[4];
    #pragma unroll
    for (int j = 0; j < 4; j++) {
        h[j] = __float2bfloat16(fs[j]);
        l[j] = __float2bfloat16(fs[j] - __bfloat162float(h[j]));
    }
    __nv_bfloat162* hp = (__nv_bfloat162*)hi;
    __nv_bfloat162* lp = (__nv_bfloat162*)lo;
    __nv_bfloat162 v;
    v.x = h[0]; v.y = h[1]; hp[2 * i] = v;
    v.x = h[2]; v.y = h[3]; hp[2 * i + 1] = v;
    v.x = l[0]; v.y = l[1]; lp[2 * i] = v;
    v.x = l[2]; v.y = l[3]; lp[2 * i + 1] = v;
}

// W[K,N] row-major -> T[N,K] bf16 hi/lo
__global__ void __launch_bounds__(256)
transpose_split(const float* __restrict__ W, __nv_bfloat16* __restrict__ Th,
                __nv_bfloat16* __restrict__ Tl, int K, int N)
{
    __shared__ float t[32][33];
    int n0 = blockIdx.x * 32, k0 = blockIdx.y * 32;
    int tx = threadIdx.x & 31, ty = threadIdx.x >> 5;
    #pragma unroll
    for (int i = 0; i < 4; i++)
        t[ty + i * 8][tx] = W[(size_t)(k0 + ty + i * 8) * N + n0 + tx];
    __syncthreads();
    #pragma unroll
    for (int i = 0; i < 4; i++) {
        float f = t[tx][ty + i * 8];
        __nv_bfloat16 h = __float2bfloat16(f);
        __nv_bfloat16 l = __float2bfloat16(f - __bfloat162float(h));
        size_t o = (size_t)(n0 + ty + i * 8) * K + k0 + tx;
        Th[o] = h; Tl[o] = l;
    }
}

// ===================== split-bf16 mma.sync GEMM =====================
// C[128x128] = A[M,2048] @ B^T, B stored [N,2048] K-major, hi/lo split.
// MODE 0: store row-major [M, Ntot]; MODE 1: RMSNorm+RoPE -> [b,h,s,hd];
// MODE 2: plain -> [b,h,s,hd]
#define BMg 128
#define BNg 128
#define BKg 32
#define GK 2048
#define NCH (GK / BKg)          // 64
#define APAD 40                 // bf16 elems per row (80 B)
#define TILE_B (128 * APAD * 2) // 10240 B per tile
#define STAGE_B (4 * TILE_B)    // Ah,Al,Bh,Bl = 40960
#define SMEM_GEMM (2 * STAGE_B) // 81920
#define CPITCH 132              // epilogue float pitch (528 B, 16B-aligned)

template<int MODE>
__global__ void __launch_bounds__(256, 1)
mma_gemm(const __nv_bfloat16* __restrict__ Ah, const __nv_bfloat16* __restrict__ Al,
         const __nv_bfloat16* __restrict__ Bh, const __nv_bfloat16* __restrict__ Bl,
         float* __restrict__ out,
         const float* __restrict__ scale, const float* __restrict__ cosp,
         const float* __restrict__ sinp, int nheads)
{
    extern __shared__ __align__(1024) char smp[];
    const uint32_t smb = smem_u32(smp);
    const int tid = threadIdx.x;
    const int lane = tid & 31, wid = tid >> 5;
    const int wm = wid >> 1, wn = wid & 1;      // 4x2 warp grid
    const int m0 = wm * 32, n0 = wn * 64;

    const size_t arow = (size_t)blockIdx.x * BMg;
    const size_t brow = (size_t)blockIdx.y * BNg;

    const int lrow = tid >> 1;                  // 0..127
    const int lc0 = (tid & 1) * 2;              // 0 or 2 (16B chunks)

    auto load_stage = [&](int ch, int p) {
        const int k0 = ch * BKg;
        uint32_t base = smb + p * STAGE_B;
        size_t ga = (arow + lrow) * GK + k0 + lc0 * 8;
        size_t gb = (brow + lrow) * GK + k0 + lc0 * 8;
        uint32_t soff = lrow * (APAD * 2) + lc0 * 16;
        #pragma unroll
        for (int j = 0; j < 2; j++) {
            cp16(base + soff + j * 16,              Ah + ga + j * 8);
            cp16(base + TILE_B + soff + j * 16,     Al + ga + j * 8);
            cp16(base + 2 * TILE_B + soff + j * 16, Bh + gb + j * 8);
            cp16(base + 3 * TILE_B + soff + j * 16, Bl + gb + j * 8);
        }
    };

    float c[2][8][4];
    #pragma unroll
    for (int i = 0; i < 2; i++)
        #pragma unroll
        for (int j = 0; j < 8; j++)
            #pragma unroll
            for (int e = 0; e < 4; e++) c[i][j][e] = 0.0f;

    load_stage(0, 0);
    CP_COMMIT();

    const uint32_t a_ro = (uint32_t)(m0 + (lane & 15)) * (APAD * 2) + ((lane >> 4) << 4);
    const uint32_t b_ro = (uint32_t)(n0 + (lane & 7) + ((lane >> 4) << 3)) * (APAD * 2)
                        + (((lane >> 3) & 1) << 4);

    for (int ch = 0; ch < NCH; ch++) {
        const int p = ch & 1;
        if (ch + 1 < NCH) load_stage(ch + 1, p ^ 1);
        CP_COMMIT();
        CP_WAIT1();
        __syncthreads();

        const uint32_t base = smb + p * STAGE_B;
        #pragma unroll
        for (int ks = 0; ks < 2; ks++) {
            uint32_t ah[2][4], al[2][4];
            #pragma unroll
            for (int mt = 0; mt < 2; mt++) {
                uint32_t ad = base + a_ro + mt * 16 * (APAD * 2) + ks * 32;
                ldm_x4(ah[mt], ad);
                ldm_x4(al[mt], ad + TILE_B);
            }
            uint32_t bh[4][4], bl[4][4];
            #pragma unroll
            for (int np = 0; np < 4; np++) {
                uint32_t bd = base + 2 * TILE_B + b_ro + np * 16 * (APAD * 2) + ks * 32;
                ldm_x4(bh[np], bd);
                ldm_x4(bl[np], bd + TILE_B);
            }
            #pragma unroll
            for (int mt = 0; mt < 2; mt++)
                #pragma unroll
                for (int nt = 0; nt < 8; nt++) {
                    const uint32_t* bhp = &bh[nt >> 1][(nt & 1) * 2];
                    const uint32_t* blp = &bl[nt >> 1][(nt & 1) * 2];
                    mma_bf16(c[mt][nt], ah[mt], bhp);
                    mma_bf16(c[mt][nt], ah[mt], blp);
                    mma_bf16(c[mt][nt], al[mt], bhp);
                }
        }
        __syncthreads();
    }

    // ---------------- epilogue ----------------
    float* Cs = (float*)smp;    // [128][CPITCH]
    const int crow = lane >> 2, ccol = (lane & 3) * 2;
    #pragma unroll
    for (int mt = 0; mt < 2; mt++)
        #pragma unroll
        for (int nt = 0; nt < 8; nt++) {
            int r = m0 + mt * 16 + crow;
            int cc = n0 + nt * 8 + ccol;
            *(float2*)&Cs[r * CPITCH + cc]       = make_float2(c[mt][nt][0], c[mt][nt][1]);
            *(float2*)&Cs[(r + 8) * CPITCH + cc] = make_float2(c[mt][nt][2], c[mt][nt][3]);
        }
    __syncthreads();

    if (MODE == 1) {
        const int r = tid & 127, hc = tid >> 7;
        float d[64];
        #pragma unroll
        for (int cc2 = 0; cc2 < 64; cc2++) d[cc2] = Cs[r * CPITCH + hc * 64 + cc2];
        float ssum = 0.0f;
        #pragma unroll
        for (int cc2 = 0; cc2 < 64; cc2++) ssum += d[cc2] * d[cc2];
        float inv = rsqrtf(ssum * (1.0f / 64.0f) + 1e-6f);
        int mglob = blockIdx.x * BMg + r;
        int s = mglob & (SS - 1);
        const float* cr = cosp + (size_t)s * 64;
        const float* sr = sinp + (size_t)s * 64;
        float outv[64];
        #pragma unroll
        for (int cc2 = 0; cc2 < 32; cc2++) {
            float a1 = d[cc2]      * inv * scale[cc2];
            float a2 = d[cc2 + 32] * inv * scale[cc2 + 32];
            outv[cc2]      = a1 * cr[cc2]      - a2 * sr[cc2];
            outv[cc2 + 32] = a2 * cr[cc2 + 32] + a1 * sr[cc2 + 32];
        }
        __syncthreads();
        #pragma unroll
        for (int cc2 = 0; cc2 < 64; cc2++) Cs[r * CPITCH + hc * 64 + cc2] = outv[cc2];
        __syncthreads();
    }

    // coalesced store
    #pragma unroll
    for (int l = 0; l < 16; l++) {
        int gi = tid + l * 256;                 // 4096 float4s
        int r = gi >> 5, c4 = gi & 31;
        int col = c4 * 4;
        float4 v = *(float4*)&Cs[r * CPITCH + col];
        int mglob = blockIdx.x * BMg + r;
        size_t oaddr;
        if (MODE == 0) {
            oaddr = (size_t)mglob * 2048 + (size_t)blockIdx.y * BNg + col;
        } else {
            int b = mglob >> 11, s = mglob & (SS - 1);
            int hg = blockIdx.y * 2 + (col >> 6);
            oaddr = (((size_t)b * nheads + hg) * SS + s) * 64 + (col & 63);
        }
        *(float4*)(out + oaddr) = v;
    }
}

// ===================== flash attention (fp32 SIMT, unchanged) =====================
__global__ void __launch_bounds__(256)
attn_kernel(const float* __restrict__ q, const float* __restrict__ k,
            const float* __restrict__ v, float* __restrict__ o_out)
{
    extern __shared__ float sm[];
    float* Qs   = sm;
    float* Ks   = Qs + 64 * 65;
    float* Ps   = Ks + 64 * 65;
    float* Vs   = Ps + 64 * 65;
    float* red  = Vs + 64 * 64;
    float* rowm = red + 64 * 16;
    float* rowl = rowm + 64;
    float* alph = rowl + 64;

    const int tid = threadIdx.x;
    const int tx = tid & 15, ty = tid >> 4;
    const int qb = blockIdx.x;
    const int bh = blockIdx.y;
    const int b = bh / NH, h = bh % NH, hk = h / RATIO;

    const size_t qbase = (((size_t)b * NH + h) * SS + (size_t)qb * 64) * HD;
    const size_t kvbase = ((size_t)b * NKV + hk) * SS * HD;

    #pragma unroll
    for (int l = 0; l < 16; l++) {
        int idx = tid + l * 256;
        int r = idx >> 6, d = idx & 63;
        Qs[r * 65 + d] = q[qbase + (size_t)r * HD + d] * 0.125f;
    }
    if (tid < 64) { rowm[tid] = -1e30f; rowl[tid] = 0.0f; }
    float o[4][4] = {};
    __syncthreads();

    for (int kb = 0; kb <= qb; kb++) {
        const size_t kt = kvbase + (size_t)kb * 64 * HD;
        #pragma unroll
        for (int l = 0; l < 16; l++) {
            int idx = tid + l * 256;
            int r = idx >> 6, d = idx & 63;
            Ks[r * 65 + d] = k[kt + (size_t)r * HD + d];
            Vs[r * 64 + d] = v[kt + (size_t)r * HD + d];
        }
        __syncthreads();

        float sv[4][4] = {};
        #pragma unroll 8
        for (int d = 0; d < 64; d++) {
            float a[4], bb[4];
            #pragma unroll
            for (int i = 0; i < 4; i++) a[i]  = Qs[(ty * 4 + i) * 65 + d];
            #pragma unroll
            for (int j = 0; j < 4; j++) bb[j] = Ks[(tx * 4 + j) * 65 + d];
            #pragma unroll
            for (int i = 0; i < 4; i++)
                #pragma unroll
                for (int j = 0; j < 4; j++)
                    sv[i][j] += a[i] * bb[j];
        }

        if (kb == qb) {
            #pragma unroll
            for (int i = 0; i < 4; i++)
                #pragma unroll
                for (int j = 0; j < 4; j++)
                    if (tx * 4 + j > ty * 4 + i) sv[i][j] = -1e30f;
        }

        #pragma unroll
        for (int i = 0; i < 4; i++) {
            float tm = fmaxf(fmaxf(sv[i][0], sv[i][1]), fmaxf(sv[i][2], sv[i][3]));
            red[(ty * 4 + i) * 16 + tx] = tm;
        }
        __syncthreads();
        if (tid < 64) {
            float tm = red[tid * 16];
            #pragma unroll
            for (int t = 1; t < 16; t++) tm = fmaxf(tm, red[tid * 16 + t]);
            float mo = rowm[tid];
            float mn = fmaxf(mo, tm);
            alph[tid] = __expf(mo - mn);
            rowm[tid] = mn;
        }
        __syncthreads();

        #pragma unroll
        for (int i = 0; i < 4; i++) {
            float mr = rowm[ty * 4 + i];
            float ps = 0.0f;
            #pragma unroll
            for (int j = 0; j < 4; j++) {
                float pp = __expf(sv[i][j] - mr);
                Ps[(ty * 4 + i) * 65 + tx * 4 + j] = pp;
                ps += pp;
            }
            red[(ty * 4 + i) * 16 + tx] = ps;
        }
        __syncthreads();
        if (tid < 64) {
            float ssum = 0.0f;
            #pragma unroll
            for (int t = 0; t < 16; t++) ssum += red[tid * 16 + t];
            rowl[tid] = rowl[tid] * alph[tid] + ssum;
        }

        #pragma unroll
        for (int i = 0; i < 4; i++) {
            float al = alph[ty * 4 + i];
            #pragma unroll
            for (int j = 0; j < 4; j++) o[i][j] *= al;
        }
        #pragma unroll 4
        for (int kk = 0; kk < 64; kk++) {
            float4 bv = *(const float4*)&Vs[kk * 64 + tx * 4];
            float bb[4] = {bv.x, bv.y, bv.z, bv.w};
            #pragma unroll
            for (int i = 0; i < 4; i++) {
                float a = Ps[(ty * 4 + i) * 65 + kk];
                #pragma unroll
                for (int j = 0; j < 4; j++) o[i][j] += a * bb[j];
            }
        }
        __syncthreads();
    }

    #pragma unroll
    for (int i = 0; i < 4; i++) {
        int r = ty * 4 + i;
        float inv = 1.0f / rowl[r];
        size_t orow = ((size_t)b * SS + (size_t)qb * 64 + r) * (NH * HD) + (size_t)h * HD;
        #pragma unroll
        for (int j = 0; j < 4; j++)
            o_out[orow + tx * 4 + j] = o[i][j] * inv;
    }
}

// ===================== launch =====================
extern "C" void kernel_launch(void* const* d_in, const int* in_sizes, int n_in,
                              void* d_out, int out_size)
{
    const float* x       = (const float*)d_in[0];
    const float* wq      = (const float*)d_in[1];
    const float* wk      = (const float*)d_in[2];
    const float* wv      = (const float*)d_in[3];
    const float* wo      = (const float*)d_in[4];
    const float* q_scale = (const float*)d_in[5];
    const float* k_scale = (const float*)d_in[6];
    const float* cosp    = (const float*)d_in[7];
    const float* sinp    = (const float*)d_in[8];

    __nv_bfloat16 *xhi, *xlo, *wqh, *wql, *wkh, *wkl, *wvh, *wvl, *woh, *wol, *ohi, *olo;
    float *gq, *gk, *gv, *go;
    cudaGetSymbolAddress((void**)&xhi, g_xhi); cudaGetSymbolAddress((void**)&xlo, g_xlo);
    cudaGetSymbolAddress((void**)&wqh, g_wqh); cudaGetSymbolAddress((void**)&wql, g_wql);
    cudaGetSymbolAddress((void**)&wkh, g_wkh); cudaGetSymbolAddress((void**)&wkl, g_wkl);
    cudaGetSymbolAddress((void**)&wvh, g_wvh); cudaGetSymbolAddress((void**)&wvl, g_wvl);
    cudaGetSymbolAddress((void**)&woh, g_woh); cudaGetSymbolAddress((void**)&wol, g_wol);
    cudaGetSymbolAddress((void**)&ohi, g_ohi); cudaGetSymbolAddress((void**)&olo, g_olo);
    cudaGetSymbolAddress((void**)&gq, g_q);   cudaGetSymbolAddress((void**)&gk, g_k);
    cudaGetSymbolAddress((void**)&gv, g_v);   cudaGetSymbolAddress((void**)&go, g_o);

    cudaFuncSetAttribute(mma_gemm<0>, cudaFuncAttributeMaxDynamicSharedMemorySize, SMEM_GEMM);
    cudaFuncSetAttribute(mma_gemm<1>, cudaFuncAttributeMaxDynamicSharedMemorySize, SMEM_GEMM);
    cudaFuncSetAttribute(mma_gemm<2>, cudaFuncAttributeMaxDynamicSharedMemorySize, SMEM_GEMM);

    // ---- conversions ----
    int n4x = (MROWS * DD) / 4;
    split_kernel<<<(n4x + 255) / 256, 256>>>(x, xhi, xlo, n4x);
    transpose_split<<<dim3((NH * HD) / 32, DD / 32), 256>>>(wq, wqh, wql, DD, NH * HD);
    transpose_split<<<dim3((NKV * HD) / 32, DD / 32), 256>>>(wk, wkh, wkl, DD, NKV * HD);
    transpose_split<<<dim3((NKV * HD) / 32, DD / 32), 256>>>(wv, wvh, wvl, DD, NKV * HD);
    transpose_split<<<dim3(DD / 32, (NH * HD) / 32), 256>>>(wo, woh, wol, NH * HD, DD);

    // ---- projections (mma.sync split-bf16) ----
    mma_gemm<1><<<dim3(MROWS / BMg, (NH * HD) / BNg), 256, SMEM_GEMM>>>(
        xhi, xlo, wqh, wql, gq, q_scale, cosp, sinp, NH);
    mma_gemm<1><<<dim3(MROWS / BMg, (NKV * HD) / BNg), 256, SMEM_GEMM>>>(
        xhi, xlo, wkh, wkl, gk, k_scale, cosp, sinp, NKV);
    mma_gemm<2><<<dim3(MROWS / BMg, (NKV * HD) / BNg), 256, SMEM_GEMM>>>(
        xhi, xlo, wvh, wvl, gv, nullptr, nullptr, nullptr, NKV);

    // ---- attention ----
    size_t smem_attn = (size_t)(64 * 65 * 3 + 64 * 64 + 64 * 16 + 64 * 3) * sizeof(float);
    cudaFuncSetAttribute(attn_kernel, cudaFuncAttributeMaxDynamicSharedMemorySize, (int)smem_attn);
    attn_kernel<<<dim3(SS / 64, BB * NH), 256, smem_attn>>>(gq, gk, gv, go);

    // ---- output projection ----
    int n4o = (MROWS * NH * HD) / 4;
    split_kernel<<<(n4o + 255) / 256, 256>>>(go, ohi, olo, n4o);
    mma_gemm<0><<<dim3(MROWS / BMg, DD / BNg), 256, SMEM_GEMM>>>(
        ohi, olo, woh, wol, (float*)d_out, nullptr, nullptr, nullptr, 0);
}

// round 5
// speedup vs baseline: 2.5553x; 1.5322x over previous
#include <cuda_runtime.h>
#include <cuda_bf16.h>
#include <math.h>
#include <stdint.h>

#define BB 2
#define SS 2048
#define DD 2048
#define NH 32
#define NKV 8
#define HD 64
#define RATIO 4
#define MROWS (BB * SS)   // 4096

// ===================== helpers =====================
__device__ __forceinline__ uint32_t smem_u32(const void* p) {
    uint32_t a;
    asm("{ .reg .u64 t; cvta.to.shared.u64 t, %1; cvt.u32.u64 %0, t; }"
        : "=r"(a) : "l"(p));
    return a;
}
__device__ __forceinline__ void cp16(uint32_t dst, const void* src) {
    asm volatile("cp.async.cg.shared.global [%0], [%1], 16;" :: "r"(dst), "l"(src));
}
#define CP_COMMIT() asm volatile("cp.async.commit_group;" ::: "memory")
#define CP_WAIT1()  asm volatile("cp.async.wait_group 1;" ::: "memory")
#define CP_WAIT0()  asm volatile("cp.async.wait_group 0;" ::: "memory")

__device__ __forceinline__ void ldm_x4(uint32_t* r, uint32_t addr) {
    asm volatile("ldmatrix.sync.aligned.m8n8.x4.shared.b16 {%0,%1,%2,%3}, [%4];"
                 : "=r"(r[0]), "=r"(r[1]), "=r"(r[2]), "=r"(r[3]) : "r"(addr));
}
__device__ __forceinline__ void ldm_x4_t(uint32_t* r, uint32_t addr) {
    asm volatile("ldmatrix.sync.aligned.m8n8.x4.trans.shared.b16 {%0,%1,%2,%3}, [%4];"
                 : "=r"(r[0]), "=r"(r[1]), "=r"(r[2]), "=r"(r[3]) : "r"(addr));
}
__device__ __forceinline__ void mma_bf16(float* d, const uint32_t* a, const uint32_t* b) {
    asm volatile("mma.sync.aligned.m16n8k16.row.col.f32.bf16.bf16.f32 "
                 "{%0,%1,%2,%3}, {%4,%5,%6,%7}, {%8,%9}, {%0,%1,%2,%3};"
                 : "+f"(d[0]), "+f"(d[1]), "+f"(d[2]), "+f"(d[3])
                 : "r"(a[0]), "r"(a[1]), "r"(a[2]), "r"(a[3]), "r"(b[0]), "r"(b[1]));
}
__device__ __forceinline__ uint32_t pack2bf(float lo, float hi) {
    uint32_t r;
    asm("cvt.rn.bf16x2.f32 %0, %1, %2;" : "=r"(r) : "f"(hi), "f"(lo));
    return r;
}
__device__ __forceinline__ void split2(float a, float b, uint32_t& hi2, uint32_t& lo2) {
    float ah = __bfloat162float(__float2bfloat16(a));
    float bh = __bfloat162float(__float2bfloat16(b));
    hi2 = pack2bf(a, b);
    lo2 = pack2bf(a - ah, b - bh);
}
// fast exp(x) for x <= 0: FFMA/ALU only (no MUFU)
__device__ __forceinline__ float fexp(float x) {
    float z = x * 1.4426950408889634f;
    z = fmaxf(z, -126.0f);
    float t = z + 12582912.0f;               // round-to-nearest via magic
    int   n = __float_as_int(t) - 0x4B400000;
    float f = z - (t - 12582912.0f);         // f in [-0.5, 0.5]
    float p = 1.540353e-4f;
    p = fmaf(p, f, 1.3333558e-3f);
    p = fmaf(p, f, 9.6181291e-3f);
    p = fmaf(p, f, 5.5504109e-2f);
    p = fmaf(p, f, 2.4022651e-1f);
    p = fmaf(p, f, 6.9314718e-1f);
    p = fmaf(p, f, 1.0f);
    return __int_as_float(__float_as_int(p) + (n << 23));
}

// ===================== scratch =====================
__device__ __nv_bfloat16 g_xhi[(size_t)MROWS * DD];
__device__ __nv_bfloat16 g_xlo[(size_t)MROWS * DD];
__device__ __nv_bfloat16 g_wqh[(size_t)(NH * HD) * DD];
__device__ __nv_bfloat16 g_wql[(size_t)(NH * HD) * DD];
__device__ __nv_bfloat16 g_wkh[(size_t)(NKV * HD) * DD];
__device__ __nv_bfloat16 g_wkl[(size_t)(NKV * HD) * DD];
__device__ __nv_bfloat16 g_wvh[(size_t)(NKV * HD) * DD];
__device__ __nv_bfloat16 g_wvl[(size_t)(NKV * HD) * DD];
__device__ __nv_bfloat16 g_woh[(size_t)DD * (NH * HD)];
__device__ __nv_bfloat16 g_wol[(size_t)DD * (NH * HD)];
__device__ __nv_bfloat16 g_qh[(size_t)BB * NH * SS * HD];
__device__ __nv_bfloat16 g_ql[(size_t)BB * NH * SS * HD];
__device__ __nv_bfloat16 g_kh[(size_t)BB * NKV * SS * HD];
__device__ __nv_bfloat16 g_kl[(size_t)BB * NKV * SS * HD];
__device__ __nv_bfloat16 g_vh[(size_t)BB * NKV * SS * HD];
__device__ __nv_bfloat16 g_vl[(size_t)BB * NKV * SS * HD];
__device__ __nv_bfloat16 g_ohi[(size_t)MROWS * (NH * HD)];
__device__ __nv_bfloat16 g_olo[(size_t)MROWS * (NH * HD)];

// ===================== conversion kernels =====================
__global__ void __launch_bounds__(256)
split_kernel(const float* __restrict__ src, __nv_bfloat16* __restrict__ hi,
             __nv_bfloat16* __restrict__ lo, int n4)
{
    int i = blockIdx.x * 256 + threadIdx.x;
    if (i >= n4) return;
    float4 f = ((const float4*)src)[i];
    float fs[4] = {f.x, f.y, f.z, f.w};
    __nv_bfloat16 h[4], l[4];
    #pragma unroll
    for (int j = 0; j < 4; j++) {
        h[j] = __float2bfloat16(fs[j]);
        l[j] = __float2bfloat16(fs[j] - __bfloat162float(h[j]));
    }
    __nv_bfloat162* hp = (__nv_bfloat162*)hi;
    __nv_bfloat162* lp = (__nv_bfloat162*)lo;
    __nv_bfloat162 v;
    v.x = h[0]; v.y = h[1]; hp[2 * i] = v;
    v.x = h[2]; v.y = h[3]; hp[2 * i + 1] = v;
    v.x = l[0]; v.y = l[1]; lp[2 * i] = v;
    v.x = l[2]; v.y = l[3]; lp[2 * i + 1] = v;
}

__global__ void __launch_bounds__(256)
transpose_split(const float* __restrict__ W, __nv_bfloat16* __restrict__ Th,
                __nv_bfloat16* __restrict__ Tl, int K, int N)
{
    __shared__ float t[32][33];
    int n0 = blockIdx.x * 32, k0 = blockIdx.y * 32;
    int tx = threadIdx.x & 31, ty = threadIdx.x >> 5;
    #pragma unroll
    for (int i = 0; i < 4; i++)
        t[ty + i * 8][tx] = W[(size_t)(k0 + ty + i * 8) * N + n0 + tx];
    __syncthreads();
    #pragma unroll
    for (int i = 0; i < 4; i++) {
        float f = t[tx][ty + i * 8];
        __nv_bfloat16 h = __float2bfloat16(f);
        __nv_bfloat16 l = __float2bfloat16(f - __bfloat162float(h));
        size_t o = (size_t)(n0 + ty + i * 8) * K + k0 + tx;
        Th[o] = h; Tl[o] = l;
    }
}

// ===================== split-bf16 mma.sync GEMM =====================
#define BMg 128
#define BNg 128
#define BKg 32
#define GK 2048
#define NCH (GK / BKg)
#define APAD 40
#define TILE_B (128 * APAD * 2)
#define STAGE_B (4 * TILE_B)
#define SMEM_GEMM (2 * STAGE_B)
#define CPITCH 132

// MODE 0: fp32 store row-major; MODE 1: RMSNorm+RoPE(+qscale) -> bf16 hi/lo [b,h,s,hd];
// MODE 2: plain -> bf16 hi/lo [b,h,s,hd]
template<int MODE>
__global__ void __launch_bounds__(256, 1)
mma_gemm(const __nv_bfloat16* __restrict__ Ah, const __nv_bfloat16* __restrict__ Al,
         const __nv_bfloat16* __restrict__ Bh, const __nv_bfloat16* __restrict__ Bl,
         float* __restrict__ out,
         __nv_bfloat16* __restrict__ outh, __nv_bfloat16* __restrict__ outl,
         const float* __restrict__ scale, const float* __restrict__ cosp,
         const float* __restrict__ sinp, int nheads, float qsc)
{
    extern __shared__ __align__(1024) char smp[];
    const uint32_t smb = smem_u32(smp);
    const int tid = threadIdx.x;
    const int lane = tid & 31, wid = tid >> 5;
    const int wm = wid >> 1, wn = wid & 1;
    const int m0 = wm * 32, n0 = wn * 64;

    const size_t arow = (size_t)blockIdx.x * BMg;
    const size_t brow = (size_t)blockIdx.y * BNg;

    const int lrow = tid >> 1;
    const int lc0 = (tid & 1) * 2;

    auto load_stage = [&](int ch, int p) {
        const int k0 = ch * BKg;
        uint32_t base = smb + p * STAGE_B;
        size_t ga = (arow + lrow) * GK + k0 + lc0 * 8;
        size_t gb = (brow + lrow) * GK + k0 + lc0 * 8;
        uint32_t soff = lrow * (APAD * 2) + lc0 * 16;
        #pragma unroll
        for (int j = 0; j < 2; j++) {
            cp16(base + soff + j * 16,              Ah + ga + j * 8);
            cp16(base + TILE_B + soff + j * 16,     Al + ga + j * 8);
            cp16(base + 2 * TILE_B + soff + j * 16, Bh + gb + j * 8);
            cp16(base + 3 * TILE_B + soff + j * 16, Bl + gb + j * 8);
        }
    };

    float c[2][8][4];
    #pragma unroll
    for (int i = 0; i < 2; i++)
        #pragma unroll
        for (int j = 0; j < 8; j++)
            #pragma unroll
            for (int e = 0; e < 4; e++) c[i][j][e] = 0.0f;

    load_stage(0, 0);
    CP_COMMIT();

    const uint32_t a_ro = (uint32_t)(m0 + (lane & 15)) * (APAD * 2) + ((lane >> 4) << 4);
    const uint32_t b_ro = (uint32_t)(n0 + (lane & 7) + ((lane >> 4) << 3)) * (APAD * 2)
                        + (((lane >> 3) & 1) << 4);

    for (int ch = 0; ch < NCH; ch++) {
        const int p = ch & 1;
        if (ch + 1 < NCH) load_stage(ch + 1, p ^ 1);
        CP_COMMIT();
        CP_WAIT1();
        __syncthreads();

        const uint32_t base = smb + p * STAGE_B;
        #pragma unroll
        for (int ks = 0; ks < 2; ks++) {
            uint32_t ah[2][4], al[2][4];
            #pragma unroll
            for (int mt = 0; mt < 2; mt++) {
                uint32_t ad = base + a_ro + mt * 16 * (APAD * 2) + ks * 32;
                ldm_x4(ah[mt], ad);
                ldm_x4(al[mt], ad + TILE_B);
            }
            uint32_t bh[4][4], bl[4][4];
            #pragma unroll
            for (int np = 0; np < 4; np++) {
                uint32_t bd = base + 2 * TILE_B + b_ro + np * 16 * (APAD * 2) + ks * 32;
                ldm_x4(bh[np], bd);
                ldm_x4(bl[np], bd + TILE_B);
            }
            #pragma unroll
            for (int mt = 0; mt < 2; mt++)
                #pragma unroll
                for (int nt = 0; nt < 8; nt++) {
                    const uint32_t* bhp = &bh[nt >> 1][(nt & 1) * 2];
                    const uint32_t* blp = &bl[nt >> 1][(nt & 1) * 2];
                    mma_bf16(c[mt][nt], ah[mt], bhp);
                    mma_bf16(c[mt][nt], ah[mt], blp);
                    mma_bf16(c[mt][nt], al[mt], bhp);
                }
        }
        __syncthreads();
    }

    // ---------------- epilogue ----------------
    float* Cs = (float*)smp;
    const int crow = lane >> 2, ccol = (lane & 3) * 2;
    #pragma unroll
    for (int mt = 0; mt < 2; mt++)
        #pragma unroll
        for (int nt = 0; nt < 8; nt++) {
            int r = m0 + mt * 16 + crow;
            int cc = n0 + nt * 8 + ccol;
            *(float2*)&Cs[r * CPITCH + cc]       = make_float2(c[mt][nt][0], c[mt][nt][1]);
            *(float2*)&Cs[(r + 8) * CPITCH + cc] = make_float2(c[mt][nt][2], c[mt][nt][3]);
        }
    __syncthreads();

    if (MODE == 1) {
        const int r = tid & 127, hc = tid >> 7;
        float d[64];
        #pragma unroll
        for (int cc2 = 0; cc2 < 64; cc2++) d[cc2] = Cs[r * CPITCH + hc * 64 + cc2];
        float ssum = 0.0f;
        #pragma unroll
        for (int cc2 = 0; cc2 < 64; cc2++) ssum += d[cc2] * d[cc2];
        float inv = rsqrtf(ssum * (1.0f / 64.0f) + 1e-6f);
        int mglob = blockIdx.x * BMg + r;
        int s = mglob & (SS - 1);
        const float* cr = cosp + (size_t)s * 64;
        const float* sr = sinp + (size_t)s * 64;
        float outv[64];
        #pragma unroll
        for (int cc2 = 0; cc2 < 32; cc2++) {
            float a1 = d[cc2]      * inv * scale[cc2];
            float a2 = d[cc2 + 32] * inv * scale[cc2 + 32];
            outv[cc2]      = (a1 * cr[cc2]      - a2 * sr[cc2])      * qsc;
            outv[cc2 + 32] = (a2 * cr[cc2 + 32] + a1 * sr[cc2 + 32]) * qsc;
        }
        __syncthreads();
        #pragma unroll
        for (int cc2 = 0; cc2 < 64; cc2++) Cs[r * CPITCH + hc * 64 + cc2] = outv[cc2];
        __syncthreads();
    }

    #pragma unroll
    for (int l = 0; l < 16; l++) {
        int gi = tid + l * 256;
        int r = gi >> 5, c4 = gi & 31;
        int col = c4 * 4;
        float4 v = *(float4*)&Cs[r * CPITCH + col];
        int mglob = blockIdx.x * BMg + r;
        if (MODE == 0) {
            size_t oaddr = (size_t)mglob * 2048 + (size_t)blockIdx.y * BNg + col;
            *(float4*)(out + oaddr) = v;
        } else {
            int b = mglob >> 11, s = mglob & (SS - 1);
            int hg = blockIdx.y * 2 + (col >> 6);
            size_t oaddr = (((size_t)b * nheads + hg) * SS + s) * 64 + (col & 63);
            uint32_t h2a, l2a, h2b, l2b;
            split2(v.x, v.y, h2a, l2a);
            split2(v.z, v.w, h2b, l2b);
            uint2 hh; hh.x = h2a; hh.y = h2b;
            uint2 ll; ll.x = l2a; ll.y = l2b;
            *(uint2*)(outh + oaddr) = hh;
            *(uint2*)(outl + oaddr) = ll;
        }
    }
}

// ===================== tensor-core flash attention =====================
// CTA: 128 q rows of one (b,h); kv tiles of 64; 8 warps x m16.
// smem: region0 (0..36863): Q hi/lo staging, later KV set for odd tiles, then O staging.
//       region1 (36864..73727): KV set for even tiles.
#define AP 72                       // bf16 row pitch (144 B)
#define Q_T 18432                   // one 128x72 bf16 tensor
#define KV_T 9216                   // one 64x72 bf16 tensor
#define KV_SET 36864
#define SMEM_ATT 73728

__global__ void __launch_bounds__(256, 1)
attn_mma(const __nv_bfloat16* __restrict__ qh_g, const __nv_bfloat16* __restrict__ ql_g,
         const __nv_bfloat16* __restrict__ kh_g, const __nv_bfloat16* __restrict__ kl_g,
         const __nv_bfloat16* __restrict__ vh_g, const __nv_bfloat16* __restrict__ vl_g,
         __nv_bfloat16* __restrict__ oh_g, __nv_bfloat16* __restrict__ ol_g)
{
    extern __shared__ __align__(1024) char smp[];
    const uint32_t smb = smem_u32(smp);
    const int tid = threadIdx.x, lane = tid & 31, wid = tid >> 5;
    const int qb = (int)gridDim.x - 1 - (int)blockIdx.x;   // long tiles first
    const int bh = blockIdx.y;
    const int b = bh >> 5, h = bh & 31, hk = h >> 2;
    const int m0 = wid * 16;
    const int nkb = 2 * qb + 2;

    const size_t qbase  = (((size_t)b * NH + h) * SS + (size_t)qb * 128) * 64;
    const size_t kvbase = ((size_t)b * NKV + hk) * SS * 64;

    auto load_kv = [&](int kb, uint32_t base) {
        const size_t rowb = kvbase + (size_t)kb * 64 * 64;
        #pragma unroll
        for (int i = 0; i < 8; i++) {
            int idx = tid + i * 256;
            int t = idx >> 9, rem = idx & 511;
            int r = rem >> 3, cc = rem & 7;
            const __nv_bfloat16* src =
                (t == 0) ? kh_g : (t == 1) ? kl_g : (t == 2) ? vh_g : vl_g;
            cp16(base + t * KV_T + r * 144 + cc * 16,
                 src + rowb + (size_t)r * 64 + cc * 8);
        }
    };

    // prologue: Q -> region0, KV0 -> region1
    #pragma unroll
    for (int i = 0; i < 8; i++) {
        int idx = tid + i * 256;
        int t = idx >> 10, rem = idx & 1023;
        int r = rem >> 3, cc = rem & 7;
        const __nv_bfloat16* src = (t == 0 ? qh_g : ql_g);
        cp16(smb + t * Q_T + r * 144 + cc * 16, src + qbase + (size_t)r * 64 + cc * 8);
    }
    load_kv(0, smb + KV_SET);
    CP_COMMIT();
    CP_WAIT0();
    __syncthreads();

    uint32_t qh[4][4], ql[4][4];
    #pragma unroll
    for (int kc = 0; kc < 4; kc++) {
        uint32_t ad = smb + (uint32_t)(m0 + (lane & 15)) * 144
                    + (uint32_t)(kc * 16 + ((lane >> 4) << 3)) * 2;
        ldm_x4(qh[kc], ad);
        ldm_x4(ql[kc], ad + Q_T);
    }
    __syncthreads();   // region0 free

    float o[8][4];
    #pragma unroll
    for (int j = 0; j < 8; j++)
        #pragma unroll
        for (int e = 0; e < 4; e++) o[j][e] = 0.0f;
    float rm0 = -1e30f, rm1 = -1e30f, rl0 = 0.0f, rl1 = 0.0f;

    for (int kb = 0; kb < nkb; kb++) {
        if (kb + 1 < nkb) {
            load_kv(kb + 1, smb + (((kb + 1) & 1) ? 0u : KV_SET));
            CP_COMMIT();
            CP_WAIT1();
        } else {
            CP_WAIT0();
        }
        __syncthreads();
        const uint32_t setb = smb + ((kb & 1) ? 0u : KV_SET);

        // ---- S = Q K^T ----
        float sc[8][4];
        #pragma unroll
        for (int j = 0; j < 8; j++)
            #pragma unroll
            for (int e = 0; e < 4; e++) sc[j][e] = 0.0f;

        #pragma unroll
        for (int kc = 0; kc < 4; kc++) {
            #pragma unroll
            for (int g = 0; g < 4; g++) {
                uint32_t ad = setb
                    + (uint32_t)(g * 16 + (lane & 7) + ((lane >> 4) << 3)) * 144
                    + (uint32_t)(kc * 16 + (((lane >> 3) & 1) << 3)) * 2;
                uint32_t kh4[4], kl4[4];
                ldm_x4(kh4, ad);
                ldm_x4(kl4, ad + KV_T);
                mma_bf16(sc[2 * g],     qh[kc], &kh4[0]);
                mma_bf16(sc[2 * g],     qh[kc], &kl4[0]);
                mma_bf16(sc[2 * g],     ql[kc], &kh4[0]);
                mma_bf16(sc[2 * g + 1], qh[kc], &kh4[2]);
                mma_bf16(sc[2 * g + 1], qh[kc], &kl4[2]);
                mma_bf16(sc[2 * g + 1], ql[kc], &kh4[2]);
            }
        }

        // ---- causal mask ----
        if (kb >= 2 * qb) {
            int row0 = qb * 128 + m0 + (lane >> 2);
            int col0 = kb * 64 + (lane & 3) * 2;
            #pragma unroll
            for (int nt = 0; nt < 8; nt++) {
                int cl = col0 + nt * 8;
                if (cl     > row0)     sc[nt][0] = -1e30f;
                if (cl + 1 > row0)     sc[nt][1] = -1e30f;
                if (cl     > row0 + 8) sc[nt][2] = -1e30f;
                if (cl + 1 > row0 + 8) sc[nt][3] = -1e30f;
            }
        }

        // ---- online softmax (poly exp, no MUFU) ----
        float mx0 = -1e30f, mx1 = -1e30f;
        #pragma unroll
        for (int nt = 0; nt < 8; nt++) {
            mx0 = fmaxf(mx0, fmaxf(sc[nt][0], sc[nt][1]));
            mx1 = fmaxf(mx1, fmaxf(sc[nt][2], sc[nt][3]));
        }
        mx0 = fmaxf(mx0, __shfl_xor_sync(0xffffffffu, mx0, 1));
        mx0 = fmaxf(mx0, __shfl_xor_sync(0xffffffffu, mx0, 2));
        mx1 = fmaxf(mx1, __shfl_xor_sync(0xffffffffu, mx1, 1));
        mx1 = fmaxf(mx1, __shfl_xor_sync(0xffffffffu, mx1, 2));
        float nm0 = fmaxf(rm0, mx0), nm1 = fmaxf(rm1, mx1);
        float a0 = fexp(rm0 - nm0), a1 = fexp(rm1 - nm1);
        rm0 = nm0; rm1 = nm1;
        float ps0 = 0.0f, ps1 = 0.0f;
        #pragma unroll
        for (int nt = 0; nt < 8; nt++) {
            sc[nt][0] = fexp(sc[nt][0] - rm0); ps0 += sc[nt][0];
            sc[nt][1] = fexp(sc[nt][1] - rm0); ps0 += sc[nt][1];
            sc[nt][2] = fexp(sc[nt][2] - rm1); ps1 += sc[nt][2];
            sc[nt][3] = fexp(sc[nt][3] - rm1); ps1 += sc[nt][3];
            o[nt][0] *= a0; o[nt][1] *= a0; o[nt][2] *= a1; o[nt][3] *= a1;
        }
        rl0 = rl0 * a0 + ps0;
        rl1 = rl1 * a1 + ps1;

        // ---- O += P V ----
        #pragma unroll
        for (int s = 0; s < 4; s++) {
            uint32_t ah[4], al[4];
            split2(sc[2 * s][0],     sc[2 * s][1],     ah[0], al[0]);
            split2(sc[2 * s][2],     sc[2 * s][3],     ah[1], al[1]);
            split2(sc[2 * s + 1][0], sc[2 * s + 1][1], ah[2], al[2]);
            split2(sc[2 * s + 1][2], sc[2 * s + 1][3], ah[3], al[3]);
            #pragma unroll
            for (int g = 0; g < 4; g++) {
                uint32_t ad = setb + 2 * KV_T        // Vh
                    + (uint32_t)(s * 16 + (lane & 7) + (((lane >> 3) & 1) << 3)) * 144
                    + (uint32_t)(g * 16 + ((lane >> 4) << 3)) * 2;
                uint32_t vh4[4], vl4[4];
                ldm_x4_t(vh4, ad);
                ldm_x4_t(vl4, ad + KV_T);
                mma_bf16(o[2 * g],     ah, &vh4[0]);
                mma_bf16(o[2 * g],     ah, &vl4[0]);
                mma_bf16(o[2 * g],     al, &vh4[0]);
                mma_bf16(o[2 * g + 1], ah, &vh4[2]);
                mma_bf16(o[2 * g + 1], ah, &vl4[2]);
                mma_bf16(o[2 * g + 1], al, &vh4[2]);
            }
        }
        __syncthreads();
    }

    // ---- finalize, stage O (region0), coalesced writeout ----
    rl0 += __shfl_xor_sync(0xffffffffu, rl0, 1);
    rl0 += __shfl_xor_sync(0xffffffffu, rl0, 2);
    rl1 += __shfl_xor_sync(0xffffffffu, rl1, 1);
    rl1 += __shfl_xor_sync(0xffffffffu, rl1, 2);
    float inv0 = 1.0f / rl0, inv1 = 1.0f / rl1;

    __syncthreads();
    #pragma unroll
    for (int nt = 0; nt < 8; nt++) {
        uint32_t off0 = (uint32_t)(m0 + (lane >> 2)) * 144 + (uint32_t)(nt * 8 + (lane & 3) * 2) * 2;
        uint32_t off1 = off0 + 8 * 144;
        uint32_t h2, l2;
        split2(o[nt][0] * inv0, o[nt][1] * inv0, h2, l2);
        *(uint32_t*)(smp + off0)       = h2;
        *(uint32_t*)(smp + Q_T + off0) = l2;
        split2(o[nt][2] * inv1, o[nt][3] * inv1, h2, l2);
        *(uint32_t*)(smp + off1)       = h2;
        *(uint32_t*)(smp + Q_T + off1) = l2;
    }
    __syncthreads();

    const size_t obase = ((size_t)b * SS + (size_t)qb * 128) * 2048 + (size_t)h * 64;
    #pragma unroll
    for (int i = 0; i < 4; i++) {
        int idx = tid + i * 256;
        int r = idx >> 3, cc = idx & 7;
        uint4 vh = *(uint4*)(smp + r * 144 + cc * 16);
        uint4 vl = *(uint4*)(smp + Q_T + r * 144 + cc * 16);
        size_t oa = obase + (size_t)r * 2048 + cc * 8;
        *(uint4*)(oh_g + oa) = vh;
        *(uint4*)(ol_g + oa) = vl;
    }
}

// ===================== launch =====================
extern "C" void kernel_launch(void* const* d_in, const int* in_sizes, int n_in,
                              void* d_out, int out_size)
{
    const float* x       = (const float*)d_in[0];
    const float* wq      = (const float*)d_in[1];
    const float* wk      = (const float*)d_in[2];
    const float* wv      = (const float*)d_in[3];
    const float* wo      = (const float*)d_in[4];
    const float* q_scale = (const float*)d_in[5];
    const float* k_scale = (const float*)d_in[6];
    const float* cosp    = (const float*)d_in[7];
    const float* sinp    = (const float*)d_in[8];

    __nv_bfloat16 *xhi, *xlo, *wqh, *wql, *wkh, *wkl, *wvh, *wvl, *woh, *wol;
    __nv_bfloat16 *qh, *ql, *kh, *kl, *vh, *vl, *ohi, *olo;
    cudaGetSymbolAddress((void**)&xhi, g_xhi); cudaGetSymbolAddress((void**)&xlo, g_xlo);
    cudaGetSymbolAddress((void**)&wqh, g_wqh); cudaGetSymbolAddress((void**)&wql, g_wql);
    cudaGetSymbolAddress((void**)&wkh, g_wkh); cudaGetSymbolAddress((void**)&wkl, g_wkl);
    cudaGetSymbolAddress((void**)&wvh, g_wvh); cudaGetSymbolAddress((void**)&wvl, g_wvl);
    cudaGetSymbolAddress((void**)&woh, g_woh); cudaGetSymbolAddress((void**)&wol, g_wol);
    cudaGetSymbolAddress((void**)&qh, g_qh);   cudaGetSymbolAddress((void**)&ql, g_ql);
    cudaGetSymbolAddress((void**)&kh, g_kh);   cudaGetSymbolAddress((void**)&kl, g_kl);
    cudaGetSymbolAddress((void**)&vh, g_vh);   cudaGetSymbolAddress((void**)&vl, g_vl);
    cudaGetSymbolAddress((void**)&ohi, g_ohi); cudaGetSymbolAddress((void**)&olo, g_olo);

    cudaFuncSetAttribute(mma_gemm<0>, cudaFuncAttributeMaxDynamicSharedMemorySize, SMEM_GEMM);
    cudaFuncSetAttribute(mma_gemm<1>, cudaFuncAttributeMaxDynamicSharedMemorySize, SMEM_GEMM);
    cudaFuncSetAttribute(mma_gemm<2>, cudaFuncAttributeMaxDynamicSharedMemorySize, SMEM_GEMM);
    cudaFuncSetAttribute(attn_mma,   cudaFuncAttributeMaxDynamicSharedMemorySize, SMEM_ATT);

    // ---- conversions ----
    int n4x = (MROWS * DD) / 4;
    split_kernel<<<(n4x + 255) / 256, 256>>>(x, xhi, xlo, n4x);
    transpose_split<<<dim3((NH * HD) / 32, DD / 32), 256>>>(wq, wqh, wql, DD, NH * HD);
    transpose_split<<<dim3((NKV * HD) / 32, DD / 32), 256>>>(wk, wkh, wkl, DD, NKV * HD);
    transpose_split<<<dim3((NKV * HD) / 32, DD / 32), 256>>>(wv, wvh, wvl, DD, NKV * HD);
    transpose_split<<<dim3(DD / 32, (NH * HD) / 32), 256>>>(wo, woh, wol, NH * HD, DD);

    // ---- projections: emit bf16 hi/lo directly (Q pre-scaled by 1/8) ----
    mma_gemm<1><<<dim3(MROWS / BMg, (NH * HD) / BNg), 256, SMEM_GEMM>>>(
        xhi, xlo, wqh, wql, nullptr, qh, ql, q_scale, cosp, sinp, NH, 0.125f);
    mma_gemm<1><<<dim3(MROWS / BMg, (NKV * HD) / BNg), 256, SMEM_GEMM>>>(
        xhi, xlo, wkh, wkl, nullptr, kh, kl, k_scale, cosp, sinp, NKV, 1.0f);
    mma_gemm<2><<<dim3(MROWS / BMg, (NKV * HD) / BNg), 256, SMEM_GEMM>>>(
        xhi, xlo, wvh, wvl, nullptr, vh, vl, nullptr, nullptr, nullptr, NKV, 1.0f);

    // ---- attention (tensor cores + poly softmax) ----
    attn_mma<<<dim3(SS / 128, BB * NH), 256, SMEM_ATT>>>(qh, ql, kh, kl, vh, vl, ohi, olo);

    // ---- output projection ----
    mma_gemm<0><<<dim3(MROWS / BMg, DD / BNg), 256, SMEM_GEMM>>>(
        ohi, olo, woh, wol, (float*)d_out, nullptr, nullptr,
        nullptr, nullptr, nullptr, 0, 1.0f);
}